// round 6
// baseline (speedup 1.0000x reference)
#include <cuda_runtime.h>
#include <math.h>

#define NB    32
#define SL    20
#define DIM   256
#define BEAMW 4
#define G     256          // persistent grid: 2 blocks/SM on 128+ SMs
#define NT    256          // 2 teams x 128 threads
#define TEAMS 2
#define EPSC  1e-8f
#define LNEPS 1e-5f

// per-team smem: sA transposed [64 kk][68 pad] = 17408B + sB [64 kk][64] = 16384B
#define TEAM_BYTES 33792
#define SMEM_DYN   (TEAMS * TEAM_BYTES)

#define NPOOL (NB * SL + 37 * NB * BEAMW)   // 640 token rows + 4736 reduce rows

// ---------------- static device scratch ----------------
__device__ float d_pool[NPOOL * DIM];        // [0,640): LN1 tokens; rest: reduce vectors
__device__ int   d_tab[2][NB * BEAMW][SL];   // stack tables: pool slot ids
__device__ int   d_p[2][NB * BEAMW];
__device__ int   d_q[2][NB * BEAMW];
__device__ float d_win[128 * 768];
__device__ float d_cc[128 * 512];
__device__ float d_cpart[6 * 128 * 256];     // conv partials ks6
__device__ float d_i1[4 * 128 * 1024];       // cell1 partials ks4
__device__ float d_c2[8 * 128 * 1024];       // cell2 partials ks8
__device__ float d_bscore[NB * BEAMW];
__device__ unsigned g_cnt = 0;
__device__ unsigned g_gen = 0;

// ---------------- grid barrier ----------------
__device__ __forceinline__ void gbar() {
    __syncthreads();
    if (threadIdx.x == 0) {
        volatile unsigned* gen = &g_gen;
        unsigned my = *gen;
        __threadfence();
        if (atomicAdd(&g_cnt, 1u) == (unsigned)(G - 1)) {
            g_cnt = 0;
            __threadfence();
            *gen = my + 1u;
        } else {
            while (*gen == my) { }
        }
        __threadfence();
    }
    __syncthreads();
}

// ---------------- helpers ----------------
__device__ __forceinline__ float geluf(float x) {
    return 0.5f * x * (1.0f + erff(x * 0.7071067811865476f));
}
__device__ __forceinline__ float sigmoidf_(float x) {
    return 1.0f / (1.0f + expf(-x));
}

// 256-thread block reduce, broadcast result
__device__ __forceinline__ float blockReduceSum(float v, float* sbuf) {
    int tid = threadIdx.x;
    #pragma unroll
    for (int o = 16; o > 0; o >>= 1) v += __shfl_down_sync(0xffffffffu, v, o);
    if ((tid & 31) == 0) sbuf[tid >> 5] = v;
    __syncthreads();
    if (tid == 0) {
        float r = 0.f;
        #pragma unroll
        for (int w = 0; w < 8; w++) r += sbuf[w];
        sbuf[0] = r;
    }
    __syncthreads();
    float r = sbuf[0];
    __syncthreads();
    return r;
}

// ---------------- packed f32x2 FFMA ----------------
__device__ __forceinline__ unsigned long long pack2(float lo, float hi) {
    unsigned long long r;
    asm("mov.b64 %0, {%1, %2};" : "=l"(r) : "f"(lo), "f"(hi));
    return r;
}
__device__ __forceinline__ void fma2(unsigned long long& d, unsigned long long a,
                                     unsigned long long b) {
    asm("fma.rn.f32x2 %0, %1, %2, %0;" : "+l"(d) : "l"(a), "l"(b));
}
__device__ __forceinline__ void unpack2(unsigned long long v, float& lo, float& hi) {
    asm("mov.b64 {%0, %1}, %2;" : "=f"(lo), "=f"(hi) : "l"(v));
}

// ---------------- 64x64 tile GEMM job, K-slice 128 = 2 teams x 64 (1 chunk) -----
// mode=1: A spans 4 slabs at stride 131072; element = gelu(sum + gb[k]).
// thread layout per team (128 thr): warp w rows w*16+(lane>>3)*4 .. +3 ;
// cols (lane&7)*8 .. +7. Raw partial output (no bias/act on C).
__device__ void gemm_job(const float* __restrict__ A, int lda, int mode,
                         const float* __restrict__ gb,
                         const float* __restrict__ B, int ldb,
                         int k0, float* __restrict__ C, int ldc, char* dsm) {
    int tid  = threadIdx.x;
    int team = tid >> 7;
    int ttid = tid & 127;
    float* sA = (float*)(dsm + team * TEAM_BYTES);           // [64 kk][68]
    float* sB = (float*)(dsm + team * TEAM_BYTES + 17408);   // [64 kk][64]
    int kt = k0 + team * 64;

    // stage A (transpose to [kk][row])
    {
        int k4 = ttid >> 3;        // 0..15
        int r0 = ttid & 7;
        #pragma unroll
        for (int p = 0; p < 8; p++) {
            int row = r0 + p * 8;
            float4 v = *(const float4*)(A + (size_t)row * lda + kt + k4 * 4);
            if (mode) {
                float4 v1 = *(const float4*)(A + 131072 + (size_t)row * lda + kt + k4 * 4);
                float4 v2 = *(const float4*)(A + 262144 + (size_t)row * lda + kt + k4 * 4);
                float4 v3 = *(const float4*)(A + 393216 + (size_t)row * lda + kt + k4 * 4);
                float4 bb = *(const float4*)(gb + kt + k4 * 4);
                v.x = geluf(v.x + v1.x + v2.x + v3.x + bb.x);
                v.y = geluf(v.y + v1.y + v2.y + v3.y + bb.y);
                v.z = geluf(v.z + v1.z + v2.z + v3.z + bb.z);
                v.w = geluf(v.w + v1.w + v2.w + v3.w + bb.w);
            }
            sA[(k4 * 4 + 0) * 68 + row] = v.x;
            sA[(k4 * 4 + 1) * 68 + row] = v.y;
            sA[(k4 * 4 + 2) * 68 + row] = v.z;
            sA[(k4 * 4 + 3) * 68 + row] = v.w;
        }
    }
    // stage B
    {
        int c4 = ttid & 15;
        #pragma unroll
        for (int p = 0; p < 8; p++) {
            int kloc = (ttid >> 4) + p * 8;
            *(float4*)(sB + kloc * 64 + c4 * 4) =
                *(const float4*)(B + (size_t)(kt + kloc) * ldb + c4 * 4);
        }
    }
    __syncthreads();

    int lane = ttid & 31, w = ttid >> 5;
    int arow = w * 16 + (lane >> 3) * 4;
    int bcol = (lane & 7) * 8;
    unsigned long long acc[16];
    #pragma unroll
    for (int i = 0; i < 16; i++) acc[i] = 0ull;

    #pragma unroll 8
    for (int kk = 0; kk < 64; kk++) {
        float4 av = *(const float4*)(sA + kk * 68 + arow);
        unsigned long long a0 = pack2(av.x, av.x);
        unsigned long long a1 = pack2(av.y, av.y);
        unsigned long long a2 = pack2(av.z, av.z);
        unsigned long long a3 = pack2(av.w, av.w);
        ulonglong2 b01 = *(const ulonglong2*)(sB + kk * 64 + bcol);
        ulonglong2 b23 = *(const ulonglong2*)(sB + kk * 64 + bcol + 4);
        fma2(acc[0],  a0, b01.x); fma2(acc[1],  a0, b01.y);
        fma2(acc[2],  a0, b23.x); fma2(acc[3],  a0, b23.y);
        fma2(acc[4],  a1, b01.x); fma2(acc[5],  a1, b01.y);
        fma2(acc[6],  a1, b23.x); fma2(acc[7],  a1, b23.y);
        fma2(acc[8],  a2, b01.x); fma2(acc[9],  a2, b01.y);
        fma2(acc[10], a2, b23.x); fma2(acc[11], a2, b23.y);
        fma2(acc[12], a3, b01.x); fma2(acc[13], a3, b01.y);
        fma2(acc[14], a3, b23.x); fma2(acc[15], a3, b23.y);
    }
    __syncthreads();

    float o[32];
    #pragma unroll
    for (int i = 0; i < 16; i++) unpack2(acc[i], o[2 * i], o[2 * i + 1]);

    if (team == 1) {
        float* cb = sB;    // team1's own sB region
        #pragma unroll
        for (int j = 0; j < 32; j++) cb[j * 128 + ttid] = o[j];
    }
    __syncthreads();
    if (team == 0) {
        const float* cb = (const float*)(dsm + TEAM_BYTES + 17408);
        #pragma unroll
        for (int j = 0; j < 32; j++) o[j] += cb[j * 128 + ttid];
        #pragma unroll
        for (int j = 0; j < 4; j++) {
            *(float4*)(C + (size_t)(arow + j) * ldc + bcol) =
                make_float4(o[8 * j], o[8 * j + 1], o[8 * j + 2], o[8 * j + 3]);
            *(float4*)(C + (size_t)(arow + j) * ldc + bcol + 4) =
                make_float4(o[8 * j + 4], o[8 * j + 5], o[8 * j + 6], o[8 * j + 7]);
        }
    }
    __syncthreads();
}

// ---------------- the persistent mega kernel ----------------
__global__ void __launch_bounds__(NT, 2)
mega(const float* __restrict__ sequence, const float* __restrict__ input_mask,
     const float* __restrict__ w_init, const float* __restrict__ b_init,
     const float* __restrict__ ln1_g, const float* __restrict__ ln1_b,
     const float* __restrict__ scorer_w, const float* __restrict__ scorer_b,
     const float* __restrict__ conv_w, const float* __restrict__ conv_b,
     const float* __restrict__ start,
     const float* __restrict__ wcell1_w, const float* __restrict__ wcell1_b,
     const float* __restrict__ wcell2_w, const float* __restrict__ wcell2_b,
     const float* __restrict__ ln2_g, const float* __restrict__ ln2_b,
     float* __restrict__ out) {
    extern __shared__ char dsm[];
    __shared__ float sred[8];
    __shared__ float sscore[8];
    __shared__ int   ssel[BEAMW];
    __shared__ int   sparK[BEAMW], swrpos[BEAMW], swrval[BEAMW];

    int tid = threadIdx.x;
    int bid = blockIdx.x;

    // ---- init 1: pool[0..639] = LN1(sequence @ w_init + b_init) ----
    {
        float* sX = (float*)dsm;
        for (int row = bid; row < NB * SL; row += G) {
            sX[tid] = sequence[(size_t)row * DIM + tid];
            __syncthreads();
            float acc = 0.f;
            for (int i = 0; i < DIM; i++)
                acc += sX[i] * w_init[i * DIM + tid];
            float y = acc + b_init[tid];
            float s1 = blockReduceSum(y, sred);
            float s2 = blockReduceSum(y * y, sred);
            float m = s1 * (1.0f / DIM);
            float var = s2 * (1.0f / DIM) - m * m;
            d_pool[(size_t)row * DIM + tid] =
                (y - m) * rsqrtf(var + LNEPS) * ln1_g[tid] + ln1_b[tid];
            __syncthreads();
        }
    }
    gbar();

    // ---- init 2: stack tables + first gather (K=1) ----
    if (bid < NB) {
        int n = bid;
        if (tid == 0) {
            d_tab[0][n * BEAMW][0] = n * SL + 0;
            d_tab[0][n * BEAMW][1] = n * SL + 1;
            d_p[0][n * BEAMW] = (input_mask[n * SL + 1] > 0.5f) ? 1 : 0;
            d_q[0][n * BEAMW] = 0;
        }
        __syncthreads();
        int p = d_p[0][n * BEAMW];
        float c1 = (p >= 1) ? d_pool[(size_t)(n * SL) * DIM + tid] : start[tid];
        float c2 = d_pool[(size_t)(n * SL + p) * DIM + tid];
        float cu = d_pool[(size_t)(n * SL + 2) * DIM + tid];
        d_win[n * 768 + tid]       = c1;
        d_win[n * 768 + 256 + tid] = c2;
        d_win[n * 768 + 512 + tid] = cu;
        d_cc[n * 512 + tid]        = c1;
        d_cc[n * 512 + 256 + tid]  = c2;
    }
    gbar();

    int K = 1, buf = 0;
    for (int t = 2; t <= 2 * SL - 2; t++) {
        int newK = (2 * K < BEAMW) ? 2 * K : BEAMW;
        int nb2 = buf ^ 1;

        // ---- P1: cell1 partials (ks4, 128 jobs) + conv partials (ks6, 48 jobs) ----
        if (bid < 176) {
            if (bid < 128) {
                int ks = bid & 3, ct = (bid >> 2) & 15, ri = bid >> 6;
                gemm_job(d_cc + (size_t)ri * 64 * 512, 512, 0, nullptr,
                         wcell1_w + ct * 64, 1024, ks * 128,
                         d_i1 + (size_t)ks * 131072 + (size_t)ri * 64 * 1024 + ct * 64,
                         1024, dsm);
            } else {
                int j = bid - 128;              // 48 = ks6 x ct4 x ri2
                int ks = j % 6, r2 = j / 6;
                int ct = r2 & 3, ri = r2 >> 2;
                gemm_job(d_win + (size_t)ri * 64 * 768, 768, 0, nullptr,
                         conv_w + ct * 64, 256, ks * 128,
                         d_cpart + (size_t)ks * 32768 + (size_t)ri * 64 * 256 + ct * 64,
                         256, dsm);
            }
        }
        gbar();

        // ---- P2: cell2 partials (ks8, 256 jobs); A = gelu(sum 4 i1 slabs + b1) ----
        {
            int ks = bid & 7, ct = (bid >> 3) & 15, ri = bid >> 7;
            gemm_job(d_i1 + (size_t)ri * 64 * 1024, 1024, 1, wcell1_b,
                     wcell2_w + ct * 64, 1024, ks * 128,
                     d_c2 + (size_t)ks * 131072 + (size_t)ri * 64 * 1024 + ct * 64,
                     1024, dsm);
        }
        // straggler work for blocks 0..31: scores + top-k + table updates
        if (bid < NB) {
            int n = bid;
            for (int k = 0; k < K; k++) {
                int m = n * K + k;
                float s = 0.f;
                #pragma unroll
                for (int ks = 0; ks < 6; ks++)
                    s += d_cpart[ks * 32768 + m * 256 + tid];
                float y = geluf(s + conv_b[tid]) * scorer_w[tid];
                float dot = blockReduceSum(y, sred);
                if (tid == 0) {
                    float dec = sigmoidf_(dot + scorer_b[0]);
                    int p = d_p[buf][n * BEAMW + k];
                    int q = d_q[buf][n * BEAMW + k];
                    float lp  = (p >= 1) ? 1.0f : 0.0f;
                    float cmf = (q < SL - 2) ? input_mask[n * SL + 2 + q] : 0.0f;
                    float bz  = ((lp == 0.0f) && (cmf == 0.0f)) ? 1.0f : 0.0f;
                    float rs = cmf * dec + (1.0f - cmf);
                    rs = lp * rs;
                    rs = bz + (1.0f - bz) * rs;
                    rs = logf(rs + EPSC);
                    float ss = lp * (1.0f - dec) + (1.0f - lp);
                    ss = cmf * ss;
                    ss = (1.0f - bz) * ss;
                    ss = logf(ss + EPSC);
                    sscore[k] = rs;
                    sscore[4 + k] = ss;
                }
            }
            if (tid == 0) {
                // stable top-k (concat order kept when 2K <= BEAM)
                int C2 = 2 * K;
                float sc[8];
                for (int c = 0; c < C2; c++)
                    sc[c] = (c < K) ? sscore[c] : sscore[4 + (c - K)];
                if (C2 <= BEAMW) {
                    for (int s2 = 0; s2 < C2; s2++) { ssel[s2] = s2; d_bscore[n * BEAMW + s2] = sc[s2]; }
                } else {
                    bool used[8];
                    for (int c = 0; c < C2; c++) used[c] = false;
                    for (int s2 = 0; s2 < BEAMW; s2++) {
                        int best = -1; float bv = 0.f;
                        for (int c = 0; c < C2; c++) {
                            if (used[c]) continue;
                            if (best < 0 || sc[c] > bv) { best = c; bv = sc[c]; }
                        }
                        used[best] = true;
                        ssel[s2] = best;
                        d_bscore[n * BEAMW + s2] = bv;
                    }
                }
                // table-update parameters (pool ids are deterministic)
                for (int s2 = 0; s2 < newK; s2++) {
                    int c = ssel[s2];
                    int isred = (c < K);
                    int k = isred ? c : (c - K);
                    int p = d_p[buf][n * BEAMW + k];
                    int q = d_q[buf][n * BEAMW + k];
                    int lp = (p >= 1);
                    float cmf = (q < SL - 2) ? input_mask[n * SL + 2 + q] : 0.0f;
                    int cm = (cmf > 0.5f);
                    int wr_pos = -1, newp = p, newq = q, wr_val = 0;
                    if (isred) {
                        if (lp) {
                            wr_pos = p - 1; newp = p - 1;
                            wr_val = NB * SL + (t - 2) * (NB * BEAMW) + n * BEAMW + k;
                        }
                    } else {
                        newq = q + 1;
                        if (cm) { wr_pos = p + 1; newp = p + 1; wr_val = n * SL + 2 + q; }
                    }
                    sparK[s2] = k; swrpos[s2] = wr_pos; swrval[s2] = wr_val;
                    d_p[nb2][n * BEAMW + s2] = newp;
                    d_q[nb2][n * BEAMW + s2] = newq;
                }
            }
            __syncthreads();
            // parallel table copy (newK*SL <= 80 entries)
            if (tid < newK * SL) {
                int s2 = tid / SL, d = tid % SL;
                int pk = sparK[s2];
                int v = d_tab[buf][n * BEAMW + pk][d];
                if (d == swrpos[s2]) v = swrval[s2];
                d_tab[nb2][n * BEAMW + s2][d] = v;
            }
        }
        gbar();

        // ---- P3: compose -> pool, then gather for next iteration ----
        if (bid < NB) {
            int n = bid;
            for (int k = 0; k < K; k++) {
                int m = n * K + k;
                float seg[4];
                #pragma unroll
                for (int sg = 0; sg < 4; sg++) {
                    float v = wcell2_b[sg * 256 + tid];
                    #pragma unroll
                    for (int ks = 0; ks < 8; ks++)
                        v += d_c2[ks * 131072 + m * 1024 + sg * 256 + tid];
                    seg[sg] = v;
                }
                float x = sigmoidf_(seg[0]) * d_cc[m * 512 + tid]
                        + sigmoidf_(seg[1]) * d_cc[m * 512 + 256 + tid]
                        + sigmoidf_(seg[2]) * seg[3];
                float s1 = blockReduceSum(x, sred);
                float s2 = blockReduceSum(x * x, sred);
                float mn = s1 * (1.0f / DIM);
                float var = s2 * (1.0f / DIM) - mn * mn;
                int rid = NB * SL + (t - 2) * (NB * BEAMW) + n * BEAMW + k;
                d_pool[(size_t)rid * DIM + tid] =
                    (x - mn) * rsqrtf(var + LNEPS) * ln2_g[tid] + ln2_b[tid];
            }
            // gather (tables from P2; pool rows written above by this thread at same tid)
            for (int s2 = 0; s2 < newK; s2++) {
                int m2 = n * newK + s2;
                int p = d_p[nb2][n * BEAMW + s2];
                int q = d_q[nb2][n * BEAMW + s2];
                const int* tb = d_tab[nb2][n * BEAMW + s2];
                float c1 = (p >= 1) ? d_pool[(size_t)tb[p - 1] * DIM + tid] : start[tid];
                float c2 = d_pool[(size_t)tb[p] * DIM + tid];
                float cu = (q < SL - 2) ? d_pool[(size_t)(n * SL + 2 + q) * DIM + tid] : 0.f;
                d_win[m2 * 768 + tid]       = c1;
                d_win[m2 * 768 + 256 + tid] = c2;
                d_win[m2 * 768 + 512 + tid] = cu;
                d_cc[m2 * 512 + tid]        = c1;
                d_cc[m2 * 512 + 256 + tid]  = c2;
            }
        }
        gbar();
        buf ^= 1;
        K = newK;
    }

    // ---- final: softmax over beam scores, weighted top-of-stack sum ----
    if (bid < NB) {
        int n = bid;
        float sc[BEAMW];
        float mx = -1e30f;
        #pragma unroll
        for (int k = 0; k < BEAMW; k++) {
            sc[k] = d_bscore[n * BEAMW + k];
            mx = fmaxf(mx, sc[k]);
        }
        float e[BEAMW], sum = 0.f;
        #pragma unroll
        for (int k = 0; k < BEAMW; k++) { e[k] = expf(sc[k] - mx); sum += e[k]; }
        float o = 0.f;
        #pragma unroll
        for (int k = 0; k < BEAMW; k++) {
            int p = d_p[buf][n * BEAMW + k];
            int slot = d_tab[buf][n * BEAMW + k][p];
            o += (e[k] / sum) * d_pool[(size_t)slot * DIM + tid];
        }
        out[(size_t)n * DIM + tid] = o;
    }
}

// ---------------- host launcher ----------------
extern "C" void kernel_launch(void* const* d_in, const int* in_sizes, int n_in,
                              void* d_out, int out_size) {
    const float* sequence   = (const float*)d_in[0];
    const float* input_mask = (const float*)d_in[1];
    const float* w_init     = (const float*)d_in[2];
    const float* b_init     = (const float*)d_in[3];
    const float* ln1_g      = (const float*)d_in[4];
    const float* ln1_b      = (const float*)d_in[5];
    const float* scorer_w   = (const float*)d_in[6];
    const float* scorer_b   = (const float*)d_in[7];
    const float* conv_w     = (const float*)d_in[8];
    const float* conv_b     = (const float*)d_in[9];
    const float* start      = (const float*)d_in[10];
    const float* wcell1_w   = (const float*)d_in[11];
    const float* wcell1_b   = (const float*)d_in[12];
    const float* wcell2_w   = (const float*)d_in[13];
    const float* wcell2_b   = (const float*)d_in[14];
    const float* ln2_g      = (const float*)d_in[15];
    const float* ln2_b      = (const float*)d_in[16];
    float* out = (float*)d_out;

    cudaFuncSetAttribute(mega, cudaFuncAttributeMaxDynamicSharedMemorySize, SMEM_DYN);
    mega<<<G, NT, SMEM_DYN>>>(sequence, input_mask, w_init, b_init, ln1_g, ln1_b,
                              scorer_w, scorer_b, conv_w, conv_b, start,
                              wcell1_w, wcell1_b, wcell2_w, wcell2_b, ln2_g, ln2_b, out);
}

// round 7
// speedup vs baseline: 1.1884x; 1.1884x over previous
#include <cuda_runtime.h>
#include <math.h>

#define NB    32
#define SL    20
#define DIM   256
#define BEAMW 4
#define G     128          // persistent grid (1 block/SM)
#define NT    512          // 4 teams x 128 threads
#define EPSC  1e-8f
#define LNEPS 1e-5f

// per-team smem: sA transposed [64 kk][68 pad] = 17408B + sB [64 kk][64] = 16384B
#define TEAM_BYTES 33792
#define SMEM_DYN   (4 * TEAM_BYTES)

#define NPOOL (NB * SL + 37 * NB * BEAMW)   // 640 token rows + 4736 reduce rows

// ---------------- static device scratch ----------------
__device__ float d_pool[NPOOL * DIM];        // [0,640): LN1 tokens; rest: reduce rows
__device__ int   d_tab[2][NB * BEAMW][SL];   // stack tables (pool slot ids)
__device__ int   d_p[2][NB * BEAMW];
__device__ int   d_q[2][NB * BEAMW];
__device__ int   d_asrc[2][128 * 3];         // per-row A descriptors: laster/last/cur
                                             // id>=0: pool row; -1: start; -2: zero
__device__ float d_cpart[3 * 128 * 256];     // conv partials (ks3)
__device__ float d_i1[2 * 128 * 1024];       // cell1 partials (ks2)
__device__ float d_c2[4 * 128 * 1024];       // cell2 partials (ks4)
__device__ float d_rs[128], d_ss[128];       // candidate log-scores
__device__ float d_bscore[NB * BEAMW];
__device__ unsigned g_cnt = 0;
__device__ unsigned g_gen = 0;

// ---------------- grid barrier ----------------
__device__ __forceinline__ void gbar() {
    __syncthreads();
    if (threadIdx.x == 0) {
        volatile unsigned* gen = &g_gen;
        unsigned my = *gen;
        __threadfence();
        if (atomicAdd(&g_cnt, 1u) == (unsigned)(G - 1)) {
            g_cnt = 0;
            __threadfence();
            *gen = my + 1u;
        } else {
            while (*gen == my) { }
        }
        __threadfence();
    }
    __syncthreads();
}

// ---------------- helpers ----------------
__device__ __forceinline__ float geluf(float x) {
    return 0.5f * x * (1.0f + erff(x * 0.7071067811865476f));
}
__device__ __forceinline__ float sigmoidf_(float x) {
    return 1.0f / (1.0f + expf(-x));
}

// 512 threads = two independent 256-thread halves; returns the half-sum
__device__ __forceinline__ float halfReduceSum(float v, float* sbuf) {
    int tid = threadIdx.x;
    #pragma unroll
    for (int o = 16; o > 0; o >>= 1) v += __shfl_down_sync(0xffffffffu, v, o);
    if ((tid & 31) == 0) sbuf[tid >> 5] = v;
    __syncthreads();
    int h = tid >> 8;
    float r = 0.f;
    #pragma unroll
    for (int w = 0; w < 8; w++) r += sbuf[h * 8 + w];
    __syncthreads();
    return r;
}

// ---------------- packed f32x2 FFMA ----------------
__device__ __forceinline__ unsigned long long pack2(float lo, float hi) {
    unsigned long long r;
    asm("mov.b64 %0, {%1, %2};" : "=l"(r) : "f"(lo), "f"(hi));
    return r;
}
__device__ __forceinline__ void fma2(unsigned long long& d, unsigned long long a,
                                     unsigned long long b) {
    asm("fma.rn.f32x2 %0, %1, %2, %0;" : "+l"(d) : "l"(a), "l"(b));
}
__device__ __forceinline__ void unpack2(unsigned long long v, float& lo, float& hi) {
    asm("mov.b64 {%0, %1}, %2;" : "=f"(lo), "=f"(hi) : "l"(v));
}

// ---------------- 64x64 tile GEMM job, K-slice 256 = 4 teams x 64 ----------------
// mode 0: A rows gathered from pool via descriptor seg ks (laster/last/cur).
// mode 1: A = gelu(i1_slab0 + i1_slab1 + gb[k]) at K-columns ks*256 + ...
// thread per team (128): rows w*16+(lane>>3)*4..+3, cols (lane&7)*8..+7.
__device__ void gemm_job(int mode, int ri, int ks,
                         const int* __restrict__ descr,
                         const float* __restrict__ start,
                         const float* __restrict__ gb,
                         const float* __restrict__ B, int ldb,
                         float* __restrict__ C, int ldc, char* dsm) {
    int tid  = threadIdx.x;
    int team = tid >> 7;
    int ttid = tid & 127;
    float* sA = (float*)(dsm + team * TEAM_BYTES);           // [64 kk][68]
    float* sB = (float*)(dsm + team * TEAM_BYTES + 17408);   // [64 kk][64]
    int kt = ks * 256 + team * 64;

    // stage A (transpose to [kk][row])
    {
        int k4 = ttid >> 3;            // 0..15
        int r0 = ttid & 7;
        int coff = team * 64 + k4 * 4; // 0..255 within the 256-seg
        #pragma unroll
        for (int p = 0; p < 8; p++) {
            int row = r0 + p * 8;
            int m = ri * 64 + row;
            float4 v;
            if (mode == 0) {
                int id = descr[m * 3 + ks];
                if (id >= 0)
                    v = *(const float4*)(d_pool + (size_t)id * DIM + coff);
                else if (id == -1)
                    v = *(const float4*)(start + coff);
                else
                    v = make_float4(0.f, 0.f, 0.f, 0.f);
            } else {
                const float* a0 = d_i1 + (size_t)m * 1024 + kt + k4 * 4;
                float4 x0 = *(const float4*)a0;
                float4 x1 = *(const float4*)(a0 + 131072);
                float4 bb = *(const float4*)(gb + kt + k4 * 4);
                v.x = geluf(x0.x + x1.x + bb.x);
                v.y = geluf(x0.y + x1.y + bb.y);
                v.z = geluf(x0.z + x1.z + bb.z);
                v.w = geluf(x0.w + x1.w + bb.w);
            }
            sA[(k4 * 4 + 0) * 68 + row] = v.x;
            sA[(k4 * 4 + 1) * 68 + row] = v.y;
            sA[(k4 * 4 + 2) * 68 + row] = v.z;
            sA[(k4 * 4 + 3) * 68 + row] = v.w;
        }
    }
    // stage B
    {
        int c4 = ttid & 15;
        #pragma unroll
        for (int p = 0; p < 8; p++) {
            int kloc = (ttid >> 4) + p * 8;
            *(float4*)(sB + kloc * 64 + c4 * 4) =
                *(const float4*)(B + (size_t)(kt + kloc) * ldb + c4 * 4);
        }
    }
    __syncthreads();

    int lane = ttid & 31, w = ttid >> 5;
    int arow = w * 16 + (lane >> 3) * 4;
    int bcol = (lane & 7) * 8;
    unsigned long long acc[16];
    #pragma unroll
    for (int i = 0; i < 16; i++) acc[i] = 0ull;

    #pragma unroll 8
    for (int kk = 0; kk < 64; kk++) {
        float4 av = *(const float4*)(sA + kk * 68 + arow);
        unsigned long long a0 = pack2(av.x, av.x);
        unsigned long long a1 = pack2(av.y, av.y);
        unsigned long long a2 = pack2(av.z, av.z);
        unsigned long long a3 = pack2(av.w, av.w);
        ulonglong2 b01 = *(const ulonglong2*)(sB + kk * 64 + bcol);
        ulonglong2 b23 = *(const ulonglong2*)(sB + kk * 64 + bcol + 4);
        fma2(acc[0],  a0, b01.x); fma2(acc[1],  a0, b01.y);
        fma2(acc[2],  a0, b23.x); fma2(acc[3],  a0, b23.y);
        fma2(acc[4],  a1, b01.x); fma2(acc[5],  a1, b01.y);
        fma2(acc[6],  a1, b23.x); fma2(acc[7],  a1, b23.y);
        fma2(acc[8],  a2, b01.x); fma2(acc[9],  a2, b01.y);
        fma2(acc[10], a2, b23.x); fma2(acc[11], a2, b23.y);
        fma2(acc[12], a3, b01.x); fma2(acc[13], a3, b01.y);
        fma2(acc[14], a3, b23.x); fma2(acc[15], a3, b23.y);
    }
    __syncthreads();

    float o[32];
    #pragma unroll
    for (int i = 0; i < 16; i++) unpack2(acc[i], o[2 * i], o[2 * i + 1]);

    if (team != 0) {
        float* cb = sB;
        #pragma unroll
        for (int j = 0; j < 32; j++) cb[j * 128 + ttid] = o[j];
    }
    __syncthreads();
    if (team == 0) {
        #pragma unroll
        for (int t = 1; t < 4; t++) {
            const float* cb = (const float*)(dsm + t * TEAM_BYTES + 17408);
            #pragma unroll
            for (int j = 0; j < 32; j++) o[j] += cb[j * 128 + ttid];
        }
        #pragma unroll
        for (int j = 0; j < 4; j++) {
            *(float4*)(C + (size_t)(arow + j) * ldc + bcol) =
                make_float4(o[8 * j], o[8 * j + 1], o[8 * j + 2], o[8 * j + 3]);
            *(float4*)(C + (size_t)(arow + j) * ldc + bcol + 4) =
                make_float4(o[8 * j + 4], o[8 * j + 5], o[8 * j + 6], o[8 * j + 7]);
        }
    }
    __syncthreads();
}

// ---------------- the persistent mega kernel ----------------
__global__ void __launch_bounds__(NT, 1)
mega(const float* __restrict__ sequence, const float* __restrict__ input_mask,
     const float* __restrict__ w_init, const float* __restrict__ b_init,
     const float* __restrict__ ln1_g, const float* __restrict__ ln1_b,
     const float* __restrict__ scorer_w, const float* __restrict__ scorer_b,
     const float* __restrict__ conv_w, const float* __restrict__ conv_b,
     const float* __restrict__ start,
     const float* __restrict__ wcell1_w, const float* __restrict__ wcell1_b,
     const float* __restrict__ wcell2_w, const float* __restrict__ wcell2_b,
     const float* __restrict__ ln2_g, const float* __restrict__ ln2_b,
     float* __restrict__ out) {
    extern __shared__ char dsm[];
    __shared__ float sred[16];
    __shared__ int   sparK[BEAMW], swrpos[BEAMW], swrval[BEAMW];

    int tid = threadIdx.x;
    int bid = blockIdx.x;
    int h   = tid >> 8;        // half id
    int col = tid & 255;

    // ---- init 1: pool tokens = LN1(sequence @ w_init + b_init); 2 rows/block ----
    {
        float* sX = (float*)dsm;   // [2][256]
        for (int job = bid; job < (NB * SL) / 2; job += G) {
            int row = job * 2 + h;
            sX[h * 256 + col] = sequence[(size_t)row * DIM + col];
            __syncthreads();
            float acc = 0.f;
            for (int i = 0; i < DIM; i++)
                acc += sX[h * 256 + i] * w_init[i * DIM + col];
            float y = acc + b_init[col];
            float s1 = halfReduceSum(y, sred);
            float s2 = halfReduceSum(y * y, sred);
            float m = s1 * (1.0f / DIM);
            float var = s2 * (1.0f / DIM) - m * m;
            d_pool[(size_t)row * DIM + col] =
                (y - m) * rsqrtf(var + LNEPS) * ln1_g[col] + ln1_b[col];
            __syncthreads();
        }
        // zero both descriptor buffers (padding rows -> pool row 0, harmless)
        if (bid == G - 1 && tid < 768) {
            d_asrc[0][tid] = 0;
            d_asrc[1][tid] = 0;
        }
    }
    gbar();

    // ---- init 2: stack tables + first descriptors (K=1, state buf=0) ----
    if (bid < NB && tid == 0) {
        int n = bid;
        d_tab[0][n * BEAMW][0] = n * SL + 0;
        d_tab[0][n * BEAMW][1] = n * SL + 1;
        int p = (input_mask[n * SL + 1] > 0.5f) ? 1 : 0;
        d_p[0][n * BEAMW] = p;
        d_q[0][n * BEAMW] = 0;
        d_asrc[0][n * 3 + 0] = (p >= 1) ? (n * SL + 0) : -1;   // laster (or START)
        d_asrc[0][n * 3 + 1] = n * SL + p;                      // last
        d_asrc[0][n * 3 + 2] = n * SL + 2;                      // cur (q=0)
    }
    gbar();

    int K = 1, buf = 0;
    for (int t = 2; t <= 2 * SL - 2; t++) {
        int newK = (2 * K < BEAMW) ? 2 * K : BEAMW;
        int nb2 = buf ^ 1;
        const int* dsc = d_asrc[buf];

        // ---- P1: cell1 partials (ks2: 64 jobs) + conv partials (ks3: 24 jobs) ----
        if (bid < 88) {
            if (bid < 64) {
                int ks = bid & 1, ct = (bid >> 1) & 15, ri = bid >> 5;
                gemm_job(0, ri, ks, dsc, start, nullptr,
                         wcell1_w + ct * 64, 1024,
                         d_i1 + (size_t)ks * 131072 + (size_t)ri * 64 * 1024 + ct * 64,
                         1024, dsm);
            } else {
                int j = bid - 64;              // 24 = ks3 x ct4 x ri2
                int ks = j % 3, r2 = j / 3;
                int ct = r2 & 3, ri = r2 >> 2;
                gemm_job(0, ri, ks, dsc, start, nullptr,
                         conv_w + ct * 64, 256,
                         d_cpart + (size_t)ks * 32768 + (size_t)ri * 64 * 256 + ct * 64,
                         256, dsm);
            }
        }
        gbar();

        // ---- P2: cell2 partials (ks4: 128 jobs) + distributed scores tail ----
        {
            int ks = bid & 3, ct = (bid >> 2) & 15, ri = bid >> 6;
            gemm_job(1, ri, ks, nullptr, nullptr, wcell1_b,
                     wcell2_w + ct * 64, 1024,
                     d_c2 + (size_t)ks * 131072 + (size_t)ri * 64 * 1024 + ct * 64,
                     1024, dsm);
        }
        if (bid < 64) {      // 2 scores per block (one per half)
            int m = 2 * bid + h;
            int valid = (m < NB * K);
            int mm = valid ? m : 0;
            float s = d_cpart[mm * 256 + col]
                    + d_cpart[32768 + mm * 256 + col]
                    + d_cpart[65536 + mm * 256 + col];
            float y = valid ? geluf(s + conv_b[col]) * scorer_w[col] : 0.f;
            float dot = halfReduceSum(y, sred);
            if (col == 0 && valid) {
                int n = mm / K, k = mm % K;
                float dec = sigmoidf_(dot + scorer_b[0]);
                int p = d_p[buf][n * BEAMW + k];
                int q = d_q[buf][n * BEAMW + k];
                float lp  = (p >= 1) ? 1.0f : 0.0f;
                float cmf = (q < SL - 2) ? input_mask[n * SL + 2 + q] : 0.0f;
                float bz  = ((lp == 0.0f) && (cmf == 0.0f)) ? 1.0f : 0.0f;
                float rs = cmf * dec + (1.0f - cmf);
                rs = lp * rs;
                rs = bz + (1.0f - bz) * rs;
                rs = logf(rs + EPSC);
                float ss = lp * (1.0f - dec) + (1.0f - lp);
                ss = cmf * ss;
                ss = (1.0f - bz) * ss;
                ss = logf(ss + EPSC);
                d_rs[mm] = rs;
                d_ss[mm] = ss;
            }
        }
        gbar();

        // ---- P3: top-k + tables + next descriptors (blocks 0-31)
        //          in parallel with compose (blocks 0-63, 2 rows each) ----
        if (bid < NB) {
            int n = bid;
            if (tid == 0) {
                int C2 = 2 * K;
                float sc[8];
                for (int c = 0; c < C2; c++)
                    sc[c] = (c < K) ? d_rs[n * K + c] : d_ss[n * K + (c - K)];
                int sel[BEAMW];
                if (C2 <= BEAMW) {
                    for (int s2 = 0; s2 < C2; s2++) { sel[s2] = s2; d_bscore[n * BEAMW + s2] = sc[s2]; }
                } else {
                    bool used[8];
                    for (int c = 0; c < C2; c++) used[c] = false;
                    for (int s2 = 0; s2 < BEAMW; s2++) {
                        int best = -1; float bv = 0.f;
                        for (int c = 0; c < C2; c++) {
                            if (used[c]) continue;
                            if (best < 0 || sc[c] > bv) { best = c; bv = sc[c]; }
                        }
                        used[best] = true;
                        sel[s2] = best;
                        d_bscore[n * BEAMW + s2] = bv;
                    }
                }
                for (int s2 = 0; s2 < newK; s2++) {
                    int c = sel[s2];
                    int isred = (c < K);
                    int k = isred ? c : (c - K);
                    int p = d_p[buf][n * BEAMW + k];
                    int q = d_q[buf][n * BEAMW + k];
                    int lp = (p >= 1);
                    float cmf = (q < SL - 2) ? input_mask[n * SL + 2 + q] : 0.0f;
                    int cm = (cmf > 0.5f);
                    int wr_pos = -1, newp = p, newq = q, wr_val = 0;
                    if (isred) {
                        if (lp) {
                            wr_pos = p - 1; newp = p - 1;
                            wr_val = NB * SL + (t - 2) * (NB * BEAMW) + n * BEAMW + k;
                        }
                    } else {
                        newq = q + 1;
                        if (cm) { wr_pos = p + 1; newp = p + 1; wr_val = n * SL + 2 + q; }
                    }
                    sparK[s2] = k; swrpos[s2] = wr_pos; swrval[s2] = wr_val;
                    d_p[nb2][n * BEAMW + s2] = newp;
                    d_q[nb2][n * BEAMW + s2] = newq;
                    // descriptors for next iteration (new table values, no copy wait)
                    const int* ot = d_tab[buf][n * BEAMW + k];
                    int laster = -1;
                    if (newp >= 1) {
                        int d = newp - 1;
                        laster = (d == wr_pos) ? wr_val : ot[d];
                    }
                    int lastv = (newp == wr_pos) ? wr_val : ot[newp];
                    int curv  = (newq < SL - 2) ? (n * SL + 2 + newq) : -2;
                    int m2 = n * newK + s2;
                    d_asrc[nb2][m2 * 3 + 0] = laster;
                    d_asrc[nb2][m2 * 3 + 1] = lastv;
                    d_asrc[nb2][m2 * 3 + 2] = curv;
                }
            }
            __syncthreads();
            // parallel table copy (newK*SL <= 80 entries)
            if (tid < newK * SL) {
                int s2 = tid / SL, d = tid % SL;
                int pk = sparK[s2];
                int v = d_tab[buf][n * BEAMW + pk][d];
                if (d == swrpos[s2]) v = swrval[s2];
                d_tab[nb2][n * BEAMW + s2][d] = v;
            }
            __syncthreads();
        }
        if (bid < 64) {      // compose: 2 rows per block (one per half)
            int m = 2 * bid + h;
            int valid = (m < NB * K);
            int mm = valid ? m : 0;
            const float* c0 = d_c2 + (size_t)mm * 1024;
            float seg[4];
            #pragma unroll
            for (int sg = 0; sg < 4; sg++) {
                seg[sg] = c0[sg * 256 + col]
                        + c0[131072 + sg * 256 + col]
                        + c0[262144 + sg * 256 + col]
                        + c0[393216 + sg * 256 + col]
                        + wcell2_b[sg * 256 + col];
            }
            int id1 = dsc[mm * 3 + 0];
            int id2 = dsc[mm * 3 + 1];
            float c1 = (id1 >= 0) ? d_pool[(size_t)id1 * DIM + col] : start[col];
            float c2v = d_pool[(size_t)id2 * DIM + col];
            float x = sigmoidf_(seg[0]) * c1
                    + sigmoidf_(seg[1]) * c2v
                    + sigmoidf_(seg[2]) * seg[3];
            float xm = valid ? x : 0.f;
            float s1 = halfReduceSum(xm, sred);
            float s2 = halfReduceSum(xm * xm, sred);
            if (valid) {
                float mn = s1 * (1.0f / DIM);
                float var = s2 * (1.0f / DIM) - mn * mn;
                int n = mm / K, k = mm % K;
                int rid = NB * SL + (t - 2) * (NB * BEAMW) + n * BEAMW + k;
                d_pool[(size_t)rid * DIM + col] =
                    (x - mn) * rsqrtf(var + LNEPS) * ln2_g[col] + ln2_b[col];
            }
        }
        gbar();
        buf ^= 1;
        K = newK;
    }

    // ---- final: softmax over beam scores, weighted top-of-stack sum ----
    if (bid < NB && h == 0) {
        int n = bid;
        float sc[BEAMW];
        float mx = -1e30f;
        #pragma unroll
        for (int k = 0; k < BEAMW; k++) {
            sc[k] = d_bscore[n * BEAMW + k];
            mx = fmaxf(mx, sc[k]);
        }
        float e[BEAMW], sum = 0.f;
        #pragma unroll
        for (int k = 0; k < BEAMW; k++) { e[k] = expf(sc[k] - mx); sum += e[k]; }
        float o = 0.f;
        #pragma unroll
        for (int k = 0; k < BEAMW; k++) {
            int p = d_p[buf][n * BEAMW + k];
            int slot = d_tab[buf][n * BEAMW + k][p];
            o += (e[k] / sum) * d_pool[(size_t)slot * DIM + col];
        }
        out[(size_t)n * DIM + col] = o;
    }
}

// ---------------- host launcher ----------------
extern "C" void kernel_launch(void* const* d_in, const int* in_sizes, int n_in,
                              void* d_out, int out_size) {
    const float* sequence   = (const float*)d_in[0];
    const float* input_mask = (const float*)d_in[1];
    const float* w_init     = (const float*)d_in[2];
    const float* b_init     = (const float*)d_in[3];
    const float* ln1_g      = (const float*)d_in[4];
    const float* ln1_b      = (const float*)d_in[5];
    const float* scorer_w   = (const float*)d_in[6];
    const float* scorer_b   = (const float*)d_in[7];
    const float* conv_w     = (const float*)d_in[8];
    const float* conv_b     = (const float*)d_in[9];
    const float* start      = (const float*)d_in[10];
    const float* wcell1_w   = (const float*)d_in[11];
    const float* wcell1_b   = (const float*)d_in[12];
    const float* wcell2_w   = (const float*)d_in[13];
    const float* wcell2_b   = (const float*)d_in[14];
    const float* ln2_g      = (const float*)d_in[15];
    const float* ln2_b      = (const float*)d_in[16];
    float* out = (float*)d_out;

    cudaFuncSetAttribute(mega, cudaFuncAttributeMaxDynamicSharedMemorySize, SMEM_DYN);
    mega<<<G, NT, SMEM_DYN>>>(sequence, input_mask, w_init, b_init, ln1_g, ln1_b,
                              scorer_w, scorer_b, conv_w, conv_b, start,
                              wcell1_w, wcell1_b, wcell2_w, wcell2_b, ln2_g, ln2_b, out);
}